// round 14
// baseline (speedup 1.0000x reference)
#include <cuda_runtime.h>
#include <math.h>

#define BN 32     // B*C images
#define HH 256
#define WW 256
#define TILE 16   // output rows per block
#define HALO 2    // shared halo rows each side (window r<=2 exact)
#define SROWS (TILE + 2*HALO)   // 20
#define FG_INF 1e6f
#define BIGF   3.0e38f          // padding: r2 + BIGF never wins, no overflow

__device__ __forceinline__ float sqrt_approx(float x) {
    float y;                    // x < 0 -> NaN (used for NaN passthrough)
    asm("sqrt.approx.f32 %0, %1;" : "=f"(y) : "f"(x));
    return y;
}

// exact per-pixel row distance recompute from x (cold path, ~never taken)
__device__ __forceinline__ float row_g_global(const float* __restrict__ xrow, int j) {
    if (xrow[j] == 0.0f) return 0.0f;
    int dl = 1 << 30, dr = 1 << 30;
    for (int t = j - 1; t >= 0; --t) if (xrow[t] == 0.0f) { dl = j - t; break; }
    for (int t = j + 1; t < WW; ++t) if (xrow[t] == 0.0f) { dr = t - j; break; }
    int d = min(dl, dr);
    if (d >= (1 << 30)) return FG_INF + fminf((float)(j + 1), (float)(WW - j));
    return (float)d;
}

// one row of phase 1: minimal hot path, warp-uniform rare fixup
__device__ __forceinline__ void do_row(float (*g2s)[WW], int lr, bool valid,
                                       const float* __restrict__ xv,
                                       const float* __restrict__ xr, int b) {
    if (!valid) {                       // warp-uniform
        #pragma unroll
        for (int k = 0; k < 8; ++k) g2s[lr][b + 32 * k] = BIGF;
        return;
    }
    unsigned mm[10];                    // bg mask words, zero-padded ends
    mm[0] = 0u; mm[9] = 0u;
    float nanprobe = 0.0f;
    #pragma unroll
    for (int k = 0; k < 8; ++k) {
        mm[k + 1] = __ballot_sync(0xFFFFFFFFu, xv[k] == 0.0f);  // NaN -> fg
        nanprobe += xv[k];
    }
    nanprobe *= 0.0f;                   // NaN iff any non-finite in lane's pixels

    int dmax = 0;
    #pragma unroll
    for (int k = 0; k < 8; ++k) {
        // self-inclusive windows: R bit t = pixel j+t ; L bit (31-t) = pixel j-t
        const unsigned R = __funnelshift_rc(mm[k + 1], mm[k + 2], b);
        const unsigned L = __funnelshift_lc(mm[k], mm[k + 1], 31 - b);
        const int d = __clz(__brev(R) | L);   // nearest bg distance, 32 if none
        dmax = max(dmax, d);
        const float fd = (float)d;
        g2s[lr][b + 32 * k] = fd * fd;
    }

    // rare fixup: far-from-bg pixels (d>=32) and/or non-finite inputs
    if (__any_sync(0xFFFFFFFFu, (dmax >= 32) || (nanprobe != nanprobe))) {
        #pragma unroll 1
        for (int k = 0; k < 8; ++k) {
            const int j = b + 32 * k;
            const unsigned R = __funnelshift_rc(mm[k + 1], mm[k + 2], b);
            const unsigned L = __funnelshift_lc(mm[k], mm[k + 1], 31 - b);
            const int d = __clz(__brev(R) | L);
            float s2;
            if (d >= 32) {
                const float g = row_g_global(xr, j);
                s2 = g * g;
            } else {
                s2 = (float)(d * d);
            }
            if (isnan(xv[k])) s2 = -s2;  // fg => s2>=1; sign bit = NaN flag
            g2s[lr][j] = s2;
        }
    }
}

__global__ void __launch_bounds__(512)
edt_fused(const float* __restrict__ x, float* __restrict__ out) {
    __shared__ float g2s[SROWS][WW];   // 20 KB; sign bit = "input was NaN"

    const int n  = blockIdx.y;                 // image
    const int i0 = blockIdx.x * TILE;          // first output row
    const int rowbase = i0 - HALO;             // global row of shared row 0
    const int b   = threadIdx.x & 31;          // lane
    const int wrp = threadIdx.x >> 5;          // 0..15

    // --- Phase 1: two rows per warp, both prefetched (MLP = 16) ---
    const int lr0 = wrp,      gr0 = rowbase + lr0;
    const int lr1 = wrp + 16, gr1 = rowbase + lr1;
    const bool in0  = (gr0 >= 0) && (gr0 < HH);
    const bool act1 = (lr1 < SROWS);
    const bool in1  = act1 && (gr1 >= 0) && (gr1 < HH);
    const float* __restrict__ xr0 = x + (n * HH + gr0) * WW;
    const float* __restrict__ xr1 = x + (n * HH + gr1) * WW;

    float xa[8], xb[8];
    if (in0) {
        #pragma unroll
        for (int k = 0; k < 8; ++k) xa[k] = xr0[b + 32 * k];
    }
    if (in1) {
        #pragma unroll
        for (int k = 0; k < 8; ++k) xb[k] = xr1[b + 32 * k];
    }

    do_row(g2s, lr0, in0, xa, xr0, b);
    if (act1) do_row(g2s, lr1, in1, xb, xr1, b);
    __syncthreads();

    // --- Phase 2: quad-column lower-envelope, r<=2 window, vote-guarded tail ---
    // thread owns columns 4qc..4qc+3 and 2 output rows.
    const int qc  = threadIdx.x & 63;          // quad-column index
    const int lo0 = (threadIdx.x >> 6) * 2;    // first local output row (0..14)

    float4 v[6];                               // shared rows lo0 .. lo0+5
    #pragma unroll
    for (int t = 0; t < 6; ++t)
        v[t] = *reinterpret_cast<const float4*>(&g2s[lo0 + t][4 * qc]);

    float needmax = 0.0f;
    #pragma unroll
    for (int p = 0; p < 2; ++p) {
        const int c = 2 + p;                   // center row in v
        // centers stay SIGNED: NaN-flagged centers are negative -> win the min
        // -> sqrt.approx(negative) = NaN output. fmaxf drops NaN (no false need).
        float bx = v[c].x, by = v[c].y, bz = v[c].z, bw = v[c].w;
        bx = fminf(bx, 1.0f + fabsf(v[c-1].x)); by = fminf(by, 1.0f + fabsf(v[c-1].y));
        bz = fminf(bz, 1.0f + fabsf(v[c-1].z)); bw = fminf(bw, 1.0f + fabsf(v[c-1].w));
        bx = fminf(bx, 1.0f + fabsf(v[c+1].x)); by = fminf(by, 1.0f + fabsf(v[c+1].y));
        bz = fminf(bz, 1.0f + fabsf(v[c+1].z)); bw = fminf(bw, 1.0f + fabsf(v[c+1].w));
        bx = fminf(bx, 4.0f + fabsf(v[c-2].x)); by = fminf(by, 4.0f + fabsf(v[c-2].y));
        bz = fminf(bz, 4.0f + fabsf(v[c-2].z)); bw = fminf(bw, 4.0f + fabsf(v[c-2].w));
        bx = fminf(bx, 4.0f + fabsf(v[c+2].x)); by = fminf(by, 4.0f + fabsf(v[c+2].y));
        bz = fminf(bz, 4.0f + fabsf(v[c+2].z)); bw = fminf(bw, 4.0f + fabsf(v[c+2].w));
        needmax = fmaxf(needmax, fmaxf(fmaxf(bx, by), fmaxf(bz, bw)));
        float4 o;
        o.x = sqrt_approx(bx); o.y = sqrt_approx(by);
        o.z = sqrt_approx(bz); o.w = sqrt_approx(bw);
        *reinterpret_cast<float4*>(
            &out[(n * HH + i0 + lo0 + p) * WW + 4 * qc]) = o;
    }

    // exact tail, warp-uniform guard, ~never taken (needs some d^2 > 9)
    if (__any_sync(0xFFFFFFFFu, needmax > 9.0f)) {
        #pragma unroll 1
        for (int e = 0; e < 8; ++e) {
            const int p = e >> 2;
            const int j = 4 * qc + (e & 3);
            const int s = HALO + lo0 + p;      // this pixel's shared row
            float best = fabsf(g2s[s][j]);
            best = fminf(best, 1.0f + fabsf(g2s[s - 1][j]));
            best = fminf(best, 1.0f + fabsf(g2s[s + 1][j]));
            best = fminf(best, 4.0f + fabsf(g2s[s - 2][j]));
            best = fminf(best, 4.0f + fabsf(g2s[s + 2][j]));
            if (best > 9.0f && !signbit(g2s[s][j])) {
                const int i = i0 + lo0 + p;    // global row
                // exact global recompute for r >= 3 (cold)
                for (int r = 3; r < HH; ++r) {
                    const float r2 = (float)(r * r);
                    if (r2 >= best) break;
                    const int up = i - r, dn = i + r;
                    if (up >= 0) {
                        const float g = row_g_global(x + (n * HH + up) * WW, j);
                        best = fminf(best, r2 + g * g);
                    }
                    if (dn < HH) {
                        const float g = row_g_global(x + (n * HH + dn) * WW, j);
                        best = fminf(best, r2 + g * g);
                    }
                }
                out[(n * HH + i) * WW + j] = sqrt_approx(best);
            }
        }
    }
}

extern "C" void kernel_launch(void* const* d_in, const int* in_sizes, int n_in,
                              void* d_out, int out_size) {
    const float* x = (const float*)d_in[0];
    float* out = (float*)d_out;
    edt_fused<<<dim3(HH / TILE, BN), 512>>>(x, out);
}

// round 15
// speedup vs baseline: 1.0269x; 1.0269x over previous
#include <cuda_runtime.h>
#include <math.h>

#define BN 32     // B*C images
#define HH 256
#define WW 256
#define TILE 16   // output rows per block
#define HALO 2    // shared halo rows each side (window r<=2 exact)
#define SROWS (TILE + 2*HALO)   // 20
#define FG_INF 1e6f
#define BIGF   3.0e38f          // padding: r2 + BIGF never wins, no overflow

__device__ __forceinline__ float sqrt_approx(float x) {
    float y;                    // x < 0 -> NaN (used for NaN passthrough)
    asm("sqrt.approx.f32 %0, %1;" : "=f"(y) : "f"(x));
    return y;
}

// exact per-pixel row distance recompute from x (cold path, ~never taken)
__device__ __forceinline__ float row_g_global(const float* __restrict__ xrow, int j) {
    if (xrow[j] == 0.0f) return 0.0f;
    int dl = 1 << 30, dr = 1 << 30;
    for (int t = j - 1; t >= 0; --t) if (xrow[t] == 0.0f) { dl = j - t; break; }
    for (int t = j + 1; t < WW; ++t) if (xrow[t] == 0.0f) { dr = t - j; break; }
    int d = min(dl, dr);
    if (d >= (1 << 30)) return FG_INF + fminf((float)(j + 1), (float)(WW - j));
    return (float)d;
}

__global__ void __launch_bounds__(512, 3)
edt_fused(const float* __restrict__ x, float* __restrict__ out) {
    __shared__ float g2s[SROWS][WW];   // 20 KB; sign bit = "input was NaN"

    const int n  = blockIdx.y;                 // image
    const int i0 = blockIdx.x * TILE;          // first output row
    const int rowbase = i0 - HALO;             // global row of shared row 0
    const int b   = threadIdx.x & 31;          // lane
    const int wrp = threadIdx.x >> 5;          // 0..15

    // --- Phase 1: row distances (warp-per-row, merged brev|clz search) ---
    #pragma unroll
    for (int pass = 0; pass < 2; ++pass) {
        const int lr = wrp + pass * 16;        // local shared row
        if (lr >= SROWS) break;                // warp-uniform
        const int gr = rowbase + lr;           // global row
        if (gr < 0 || gr >= HH) {
            #pragma unroll
            for (int k = 0; k < 8; ++k) g2s[lr][b + 32 * k] = BIGF;
            continue;
        }
        const float* __restrict__ xr = x + (n * HH + gr) * WW;

        unsigned mm[10];                       // bg mask words, zero-padded ends
        mm[0] = 0u; mm[9] = 0u;
        float nanprobe = 0.0f;
        #pragma unroll
        for (int k = 0; k < 8; ++k) {
            const float xv = xr[b + 32 * k];
            mm[k + 1] = __ballot_sync(0xFFFFFFFFu, xv == 0.0f);  // NaN -> fg
            nanprobe += xv;
        }
        nanprobe *= 0.0f;    // NaN iff any non-finite among this lane's pixels

        int dmax = 0;
        #pragma unroll
        for (int k = 0; k < 8; ++k) {
            // self-inclusive windows: R bit t = pixel j+t ; L bit (31-t) = pixel j-t
            const unsigned R = __funnelshift_rc(mm[k + 1], mm[k + 2], b);
            const unsigned L = __funnelshift_lc(mm[k], mm[k + 1], 31 - b);
            const int d = __clz(__brev(R) | L);  // nearest bg distance, 32 if none
            dmax = max(dmax, d);
            const float fd = (float)d;
            g2s[lr][b + 32 * k] = fd * fd;
        }

        // rare warp-uniform fixup: far-from-bg (d>=32) and/or non-finite inputs
        if (__any_sync(0xFFFFFFFFu, (dmax >= 32) | (nanprobe != nanprobe))) {
            #pragma unroll 1
            for (int k = 0; k < 8; ++k) {
                const int j = b + 32 * k;
                const float xv = xr[j];
                const unsigned R = __funnelshift_rc(mm[k + 1], mm[k + 2], b);
                const unsigned L = __funnelshift_lc(mm[k], mm[k + 1], 31 - b);
                const int d = __clz(__brev(R) | L);
                float s2;
                if (d >= 32) {
                    const float g = row_g_global(xr, j);
                    s2 = g * g;
                } else {
                    s2 = (float)(d * d);
                }
                if (isnan(xv)) s2 = -s2;   // fg => s2>=1; sign bit = NaN flag
                g2s[lr][j] = s2;
            }
        }
    }
    __syncthreads();

    // --- Phase 2: quad-column lower-envelope, r<=2 window, vote-guarded tail ---
    // thread owns columns 4qc..4qc+3 and 2 output rows.
    const int qc  = threadIdx.x & 63;          // quad-column index
    const int lo0 = (threadIdx.x >> 6) * 2;    // first local output row (0..14)

    float4 v[6];                               // shared rows lo0 .. lo0+5
    #pragma unroll
    for (int t = 0; t < 6; ++t)
        v[t] = *reinterpret_cast<const float4*>(&g2s[lo0 + t][4 * qc]);

    float needmax = 0.0f;
    #pragma unroll
    for (int p = 0; p < 2; ++p) {
        const int c = 2 + p;                   // center row in v
        // centers stay SIGNED: NaN-flagged centers are negative -> win the min
        // -> sqrt.approx(negative) = NaN output. fmaxf drops NaN (no false need).
        float bx = v[c].x, by = v[c].y, bz = v[c].z, bw = v[c].w;
        bx = fminf(bx, 1.0f + fabsf(v[c-1].x)); by = fminf(by, 1.0f + fabsf(v[c-1].y));
        bz = fminf(bz, 1.0f + fabsf(v[c-1].z)); bw = fminf(bw, 1.0f + fabsf(v[c-1].w));
        bx = fminf(bx, 1.0f + fabsf(v[c+1].x)); by = fminf(by, 1.0f + fabsf(v[c+1].y));
        bz = fminf(bz, 1.0f + fabsf(v[c+1].z)); bw = fminf(bw, 1.0f + fabsf(v[c+1].w));
        bx = fminf(bx, 4.0f + fabsf(v[c-2].x)); by = fminf(by, 4.0f + fabsf(v[c-2].y));
        bz = fminf(bz, 4.0f + fabsf(v[c-2].z)); bw = fminf(bw, 4.0f + fabsf(v[c-2].w));
        bx = fminf(bx, 4.0f + fabsf(v[c+2].x)); by = fminf(by, 4.0f + fabsf(v[c+2].y));
        bz = fminf(bz, 4.0f + fabsf(v[c+2].z)); bw = fminf(bw, 4.0f + fabsf(v[c+2].w));
        needmax = fmaxf(needmax, fmaxf(fmaxf(bx, by), fmaxf(bz, bw)));
        float4 o;
        o.x = sqrt_approx(bx); o.y = sqrt_approx(by);
        o.z = sqrt_approx(bz); o.w = sqrt_approx(bw);
        *reinterpret_cast<float4*>(
            &out[(n * HH + i0 + lo0 + p) * WW + 4 * qc]) = o;
    }

    // exact tail, warp-uniform guard, ~never taken (needs some d^2 > 9)
    if (__any_sync(0xFFFFFFFFu, needmax > 9.0f)) {
        #pragma unroll 1
        for (int e = 0; e < 8; ++e) {
            const int p = e >> 2;
            const int j = 4 * qc + (e & 3);
            const int s = HALO + lo0 + p;      // this pixel's shared row
            float best = fabsf(g2s[s][j]);
            best = fminf(best, 1.0f + fabsf(g2s[s - 1][j]));
            best = fminf(best, 1.0f + fabsf(g2s[s + 1][j]));
            best = fminf(best, 4.0f + fabsf(g2s[s - 2][j]));
            best = fminf(best, 4.0f + fabsf(g2s[s + 2][j]));
            if (best > 9.0f && !signbit(g2s[s][j])) {
                const int i = i0 + lo0 + p;    // global row
                // exact global recompute for r >= 3 (cold)
                for (int r = 3; r < HH; ++r) {
                    const float r2 = (float)(r * r);
                    if (r2 >= best) break;
                    const int up = i - r, dn = i + r;
                    if (up >= 0) {
                        const float g = row_g_global(x + (n * HH + up) * WW, j);
                        best = fminf(best, r2 + g * g);
                    }
                    if (dn < HH) {
                        const float g = row_g_global(x + (n * HH + dn) * WW, j);
                        best = fminf(best, r2 + g * g);
                    }
                }
                out[(n * HH + i) * WW + j] = sqrt_approx(best);
            }
        }
    }
}

extern "C" void kernel_launch(void* const* d_in, const int* in_sizes, int n_in,
                              void* d_out, int out_size) {
    const float* x = (const float*)d_in[0];
    float* out = (float*)d_out;
    edt_fused<<<dim3(HH / TILE, BN), 512>>>(x, out);
}

// round 16
// speedup vs baseline: 1.2647x; 1.2316x over previous
#include <cuda_runtime.h>
#include <math.h>

#define BN 32     // B*C images
#define HH 256
#define WW 256
#define TILE 32   // output rows per block
#define HALO 2    // shared halo rows each side (window r<=2 exact)
#define SROWS (TILE + 2*HALO)   // 36
#define FG_INF 1e6f
#define BIGF   3.0e38f          // padding: r2 + BIGF never wins, no overflow

__device__ __forceinline__ float sqrt_approx(float x) {
    float y;                    // x < 0 -> NaN (used for NaN passthrough)
    asm("sqrt.approx.f32 %0, %1;" : "=f"(y) : "f"(x));
    return y;
}

// exact per-pixel row distance recompute from x (cold path, ~never taken)
__device__ __forceinline__ float row_g_global(const float* __restrict__ xrow, int j) {
    if (xrow[j] == 0.0f) return 0.0f;
    int dl = 1 << 30, dr = 1 << 30;
    for (int t = j - 1; t >= 0; --t) if (xrow[t] == 0.0f) { dl = j - t; break; }
    for (int t = j + 1; t < WW; ++t) if (xrow[t] == 0.0f) { dr = t - j; break; }
    int d = min(dl, dr);
    if (d >= (1 << 30)) return FG_INF + fminf((float)(j + 1), (float)(WW - j));
    return (float)d;
}

__global__ void __launch_bounds__(512, 3)
edt_fused(const float* __restrict__ x, float* __restrict__ out) {
    __shared__ float g2s[SROWS][WW];   // 36 KB; sign bit = "input was NaN"

    const int n  = blockIdx.y;                 // image
    const int i0 = blockIdx.x * TILE;          // first output row
    const int rowbase = i0 - HALO;             // global row of shared row 0
    const int b   = threadIdx.x & 31;          // lane
    const int wrp = threadIdx.x >> 5;          // 0..15

    // --- Phase 1: row distances (warp-per-row, merged brev|clz search) ---
    #pragma unroll
    for (int pass = 0; pass < 3; ++pass) {
        const int lr = wrp + pass * 16;        // local shared row
        if (lr >= SROWS) break;                // warp-uniform
        const int gr = rowbase + lr;           // global row
        if (gr < 0 || gr >= HH) {
            #pragma unroll
            for (int k = 0; k < 8; ++k) g2s[lr][b + 32 * k] = BIGF;
            continue;
        }
        const float* __restrict__ xr = x + (n * HH + gr) * WW;

        unsigned mm[10];                       // bg mask words, zero-padded ends
        mm[0] = 0u; mm[9] = 0u;
        float nanprobe = 0.0f;
        #pragma unroll
        for (int k = 0; k < 8; ++k) {
            const float xv = xr[b + 32 * k];
            mm[k + 1] = __ballot_sync(0xFFFFFFFFu, xv == 0.0f);  // NaN -> fg
            nanprobe += xv;
        }
        nanprobe *= 0.0f;    // NaN iff any non-finite among this lane's pixels

        int dmax = 0;
        #pragma unroll
        for (int k = 0; k < 8; ++k) {
            // self-inclusive windows: R bit t = pixel j+t ; L bit (31-t) = pixel j-t
            const unsigned R = __funnelshift_rc(mm[k + 1], mm[k + 2], b);
            const unsigned L = __funnelshift_lc(mm[k], mm[k + 1], 31 - b);
            const int d = __clz(__brev(R) | L);  // nearest bg distance, 32 if none
            dmax = max(dmax, d);
            const float fd = (float)d;
            g2s[lr][b + 32 * k] = fd * fd;
        }

        // rare warp-uniform fixup: far-from-bg (d>=32) and/or non-finite inputs
        if (__any_sync(0xFFFFFFFFu, (dmax >= 32) | (nanprobe != nanprobe))) {
            #pragma unroll 1
            for (int k = 0; k < 8; ++k) {
                const int j = b + 32 * k;
                const float xv = xr[j];
                const unsigned R = __funnelshift_rc(mm[k + 1], mm[k + 2], b);
                const unsigned L = __funnelshift_lc(mm[k], mm[k + 1], 31 - b);
                const int d = __clz(__brev(R) | L);
                float s2;
                if (d >= 32) {
                    const float g = row_g_global(xr, j);
                    s2 = g * g;
                } else {
                    s2 = (float)(d * d);
                }
                if (isnan(xv)) s2 = -s2;   // fg => s2>=1; sign bit = NaN flag
                g2s[lr][j] = s2;
            }
        }
    }
    __syncthreads();

    // --- Phase 2: quad-column lower-envelope, r<=2 window, vote-guarded tail ---
    // thread owns columns 4qc..4qc+3 and 2 output rows per sub-chunk (2 subs).
    const int qc  = threadIdx.x & 63;          // quad-column index
    const int grp = threadIdx.x >> 6;          // 0..7

    #pragma unroll
    for (int sub = 0; sub < 2; ++sub) {
        const int lo0 = grp * 2 + sub * 16;    // first local output row

        float4 v[6];                           // shared rows lo0 .. lo0+5
        #pragma unroll
        for (int t = 0; t < 6; ++t)
            v[t] = *reinterpret_cast<const float4*>(&g2s[lo0 + t][4 * qc]);

        float needmax = 0.0f;
        #pragma unroll
        for (int p = 0; p < 2; ++p) {
            const int c = 2 + p;               // center row in v
            // centers stay SIGNED: NaN-flagged centers are negative -> win the
            // min -> sqrt.approx(negative) = NaN output. fmaxf drops NaN.
            float bx = v[c].x, by = v[c].y, bz = v[c].z, bw = v[c].w;
            bx = fminf(bx, 1.0f + fabsf(v[c-1].x)); by = fminf(by, 1.0f + fabsf(v[c-1].y));
            bz = fminf(bz, 1.0f + fabsf(v[c-1].z)); bw = fminf(bw, 1.0f + fabsf(v[c-1].w));
            bx = fminf(bx, 1.0f + fabsf(v[c+1].x)); by = fminf(by, 1.0f + fabsf(v[c+1].y));
            bz = fminf(bz, 1.0f + fabsf(v[c+1].z)); bw = fminf(bw, 1.0f + fabsf(v[c+1].w));
            bx = fminf(bx, 4.0f + fabsf(v[c-2].x)); by = fminf(by, 4.0f + fabsf(v[c-2].y));
            bz = fminf(bz, 4.0f + fabsf(v[c-2].z)); bw = fminf(bw, 4.0f + fabsf(v[c-2].w));
            bx = fminf(bx, 4.0f + fabsf(v[c+2].x)); by = fminf(by, 4.0f + fabsf(v[c+2].y));
            bz = fminf(bz, 4.0f + fabsf(v[c+2].z)); bw = fminf(bw, 4.0f + fabsf(v[c+2].w));
            needmax = fmaxf(needmax, fmaxf(fmaxf(bx, by), fmaxf(bz, bw)));
            float4 o;
            o.x = sqrt_approx(bx); o.y = sqrt_approx(by);
            o.z = sqrt_approx(bz); o.w = sqrt_approx(bw);
            *reinterpret_cast<float4*>(
                &out[(n * HH + i0 + lo0 + p) * WW + 4 * qc]) = o;
        }

        // exact tail, warp-uniform guard, ~never taken (needs some d^2 > 9)
        if (__any_sync(0xFFFFFFFFu, needmax > 9.0f)) {
            #pragma unroll 1
            for (int e = 0; e < 8; ++e) {
                const int p = e >> 2;
                const int j = 4 * qc + (e & 3);
                const int s = HALO + lo0 + p;  // this pixel's shared row
                float best = fabsf(g2s[s][j]);
                best = fminf(best, 1.0f + fabsf(g2s[s - 1][j]));
                best = fminf(best, 1.0f + fabsf(g2s[s + 1][j]));
                best = fminf(best, 4.0f + fabsf(g2s[s - 2][j]));
                best = fminf(best, 4.0f + fabsf(g2s[s + 2][j]));
                if (best > 9.0f && !signbit(g2s[s][j])) {
                    const int i = i0 + lo0 + p;    // global row
                    // exact global recompute for r >= 3 (cold)
                    for (int r = 3; r < HH; ++r) {
                        const float r2 = (float)(r * r);
                        if (r2 >= best) break;
                        const int up = i - r, dn = i + r;
                        if (up >= 0) {
                            const float g = row_g_global(x + (n * HH + up) * WW, j);
                            best = fminf(best, r2 + g * g);
                        }
                        if (dn < HH) {
                            const float g = row_g_global(x + (n * HH + dn) * WW, j);
                            best = fminf(best, r2 + g * g);
                        }
                    }
                    out[(n * HH + i) * WW + j] = sqrt_approx(best);
                }
            }
        }
    }
}

extern "C" void kernel_launch(void* const* d_in, const int* in_sizes, int n_in,
                              void* d_out, int out_size) {
    const float* x = (const float*)d_in[0];
    float* out = (float*)d_out;
    edt_fused<<<dim3(HH / TILE, BN), 512>>>(x, out);
}